// round 11
// baseline (speedup 1.0000x reference)
#include <cuda_runtime.h>
#include <cstdint>

// Problem constants
#define MTOT   32768      // B*S
#define DM     512        // d_model
#define HEADS  8
#define HD     64
#define WSZ    128
#define NWIN   256

// ---------------------------------------------------------------------------
// Scratch (device globals; no runtime allocation allowed)
// ---------------------------------------------------------------------------
__device__ float g_q [MTOT * DM];
__device__ float g_k [MTOT * DM];
__device__ float g_v [MTOT * DM];
__device__ float g_ao[MTOT * DM];

// ---------------------------------------------------------------------------
// helpers
// ---------------------------------------------------------------------------
__device__ __forceinline__ uint32_t f2tf32(float f) {
    uint32_t r;
    asm("cvt.rna.tf32.f32 %0, %1;" : "=r"(r) : "f"(f));
    return r;
}

// mma.sync m16n8k8 tf32 (baseline PTX; valid on plain sm_103 target)
__device__ __forceinline__ void mma8(float* d, const uint32_t* a, const uint32_t* b) {
    asm volatile(
        "mma.sync.aligned.m16n8k8.row.col.f32.tf32.tf32.f32 "
        "{%0,%1,%2,%3}, {%4,%5,%6,%7}, {%8,%9}, {%0,%1,%2,%3};"
        : "+f"(d[0]), "+f"(d[1]), "+f"(d[2]), "+f"(d[3])
        : "r"(a[0]), "r"(a[1]), "r"(a[2]), "r"(a[3]), "r"(b[0]), "r"(b[1]));
}

// Fast exp on FMA/ALU pipes only (no MUFU, no CVT). x <= 0 here.
__device__ __forceinline__ float fexp(float x) {
    float y = x * 1.44269504088896f;
    float t = y + 12582912.f;
    float n = t - 12582912.f;
    float f = y - n;
    float p = 0.00133335581f;
    p = fmaf(p, f, 0.00961812910f);
    p = fmaf(p, f, 0.05550410866f);
    p = fmaf(p, f, 0.24022650696f);
    p = fmaf(p, f, 0.69314718056f);
    p = fmaf(p, f, 1.0f);
    int ni = __float_as_int(t) - 0x4B400000;
    float s = __int_as_float((ni + 127) << 23);
    return p * s;
}

// ---------------------------------------------------------------------------
// tf32 tensor GEMM v2: C = A*W^T + bias
// CTA 128x128, 8 warps (2m x 4n), K chunks of 32, DOUBLE-BUFFERED smem,
// one __syncthreads per chunk.
// Smem layout (per tensor per buffer): 128 rows x 40 words. Column c of a
// chunk (0..31) stored at word:
//   r*40 + (c>>3)*8 + ( (2*(c&3) + ((c&7)>>2)) ^ (2*(r&3)) )
// -> fragment pairs (tt, tt+4) are adjacent (uint2 LDS.64), and both the
//    LDS.64 compute reads and the STS.32 staging writes are bank-conflict-free.
// ---------------------------------------------------------------------------
#define KC      32
#define NCH     (DM / KC)        // 16
#define PITCHW  40
#define TBUFW   (128 * PITCHW)   // words per tensor buffer (5120)
#define GEMM_SMEM_BYTES (4 * TBUFW * 4)   // 81920

__device__ __forceinline__ void stage_frag(uint32_t* buf, int srow, int scolq,
                                           float4 v) {
    int base = srow * PITCHW + (scolq >> 1) * 8 + (scolq & 1);
    int e = 2 * (srow & 3);
    buf[base + (0 ^ e)] = f2tf32(v.x);
    buf[base + (2 ^ e)] = f2tf32(v.y);
    buf[base + (4 ^ e)] = f2tf32(v.z);
    buf[base + (6 ^ e)] = f2tf32(v.w);
}

__global__ __launch_bounds__(256, 2) void gemm_tc(
    const float* __restrict__ A, const float* __restrict__ W,
    const float* __restrict__ bias, float* __restrict__ C)
{
    extern __shared__ uint32_t smw[];
    // buffer b: A at b*2*TBUFW, W at b*2*TBUFW + TBUFW

    const int t    = threadIdx.x;
    const int warp = t >> 5;
    const int lane = t & 31;
    const int wm   = warp >> 2;
    const int wn   = warp & 3;
    const int g    = lane >> 2;
    const int tt   = lane & 3;
    const int m0   = blockIdx.y * 128;
    const int n0   = blockIdx.x * 128;
    const int esw  = 2 * (g & 3);          // compute-side XOR (row&3 == g&3)

    int srow[4], scolq[4];
#pragma unroll
    for (int e = 0; e < 4; e++) {
        int f = e * 256 + t;
        srow[e]  = f >> 3;
        scolq[e] = f & 7;
    }

    float acc[4][4][4];
#pragma unroll
    for (int mt = 0; mt < 4; mt++)
#pragma unroll
        for (int nt = 0; nt < 4; nt++)
#pragma unroll
            for (int r = 0; r < 4; r++) acc[mt][nt][r] = 0.f;

    // prefetch chunk 0
    float4 pa[4], pw[4];
#pragma unroll
    for (int e = 0; e < 4; e++) {
        pa[e] = *(const float4*)(A + (size_t)(m0 + srow[e]) * DM + scolq[e] * 4);
        pw[e] = *(const float4*)(W + (size_t)(n0 + srow[e]) * DM + scolq[e] * 4);
    }

    for (int ch = 0; ch < NCH; ch++) {
        const int buf = ch & 1;
        uint32_t* As = smw + buf * 2 * TBUFW;
        uint32_t* Ws = As + TBUFW;

        // store prefetched chunk into this buffer
#pragma unroll
        for (int e = 0; e < 4; e++) {
            stage_frag(As, srow[e], scolq[e], pa[e]);
            stage_frag(Ws, srow[e], scolq[e], pw[e]);
        }
        __syncthreads();

        // prefetch next chunk (overlaps compute below)
        if (ch + 1 < NCH) {
            const int ccol = (ch + 1) * KC;
#pragma unroll
            for (int e = 0; e < 4; e++) {
                pa[e] = *(const float4*)(A + (size_t)(m0 + srow[e]) * DM + ccol + scolq[e] * 4);
                pw[e] = *(const float4*)(W + (size_t)(n0 + srow[e]) * DM + ccol + scolq[e] * 4);
            }
        }

        // compute 4 k-steps from this buffer
#pragma unroll
        for (int ks = 0; ks < 4; ks++) {
            const int kb = ks * 8 + ((2 * tt) ^ esw);
            uint32_t a[4][4], b[4][2];
#pragma unroll
            for (int mt = 0; mt < 4; mt++) {
                int ra = (wm * 64 + mt * 16 + g) * PITCHW + kb;
                uint2 lo = *(const uint2*)&As[ra];                 // (a0, a2)
                uint2 hi = *(const uint2*)&As[ra + 8 * PITCHW];    // (a1, a3)
                a[mt][0] = lo.x; a[mt][1] = hi.x;
                a[mt][2] = lo.y; a[mt][3] = hi.y;
            }
#pragma unroll
            for (int nt = 0; nt < 4; nt++) {
                int rb = (wn * 32 + nt * 8 + g) * PITCHW + kb;
                uint2 bb = *(const uint2*)&Ws[rb];
                b[nt][0] = bb.x; b[nt][1] = bb.y;
            }
#pragma unroll
            for (int mt = 0; mt < 4; mt++)
#pragma unroll
                for (int nt = 0; nt < 4; nt++)
                    mma8(acc[mt][nt], a[mt], b[nt]);
        }
        // no second sync: next iteration writes the OTHER buffer, whose last
        // readers (chunk ch-1) are fenced by this chunk's __syncthreads.
    }

    // epilogue: bias add + store
#pragma unroll
    for (int mt = 0; mt < 4; mt++) {
        const int row0 = m0 + wm * 64 + mt * 16 + g;
#pragma unroll
        for (int nt = 0; nt < 4; nt++) {
            const int c = n0 + wn * 32 + nt * 8 + tt * 2;
            float b0 = bias[c], b1 = bias[c + 1];
            float* p0 = C + (size_t)row0 * DM + c;
            float* p1 = C + (size_t)(row0 + 8) * DM + c;
            *(float2*)p0 = make_float2(acc[mt][nt][0] + b0, acc[mt][nt][1] + b1);
            *(float2*)p1 = make_float2(acc[mt][nt][2] + b0, acc[mt][nt][3] + b1);
        }
    }
}

// ---------------------------------------------------------------------------
// Windowed attention (unchanged from round 7, validated): tensor matmuls +
// FMA-pipe softmax. One CTA per (window, head).
// ---------------------------------------------------------------------------
#define QP 68
#define SP 132
#define ATTN_SMEM_BYTES ((2 * 128 * QP + 128 * QP) * 4)   // 104448

__global__ __launch_bounds__(256, 2) void attn_kernel()
{
    extern __shared__ float smf[];
    float*    Qsf = smf;
    float*    Ksf = smf + 128 * QP;
    uint32_t* Qs  = (uint32_t*)Qsf;
    uint32_t* Ks  = (uint32_t*)Ksf;
    float*    Ss  = smf;                       // aliases Qs+Ks
    uint32_t* Ssu = (uint32_t*)Ss;
    float*    Vsf = smf + 2 * 128 * QP;
    uint32_t* Vs  = (uint32_t*)Vsf;

    const int h    = blockIdx.x;
    const int wdw  = blockIdx.y;
    const int t    = threadIdx.x;
    const int warp = t >> 5;
    const int lane = t & 31;
    const int wm   = warp >> 2;
    const int wn   = warp & 3;
    const int g    = lane >> 2;
    const int tt   = lane & 3;

    const size_t gbase = (size_t)wdw * WSZ * DM + (size_t)h * HD;

#pragma unroll
    for (int it = 0; it < 8; it++) {
        int f   = it * 256 + t;
        int row = f >> 4;
        int c4  = (f & 15) << 2;
        const float* qp = g_q + gbase + (size_t)row * DM + c4;
        const float* kp = g_k + gbase + (size_t)row * DM + c4;
        const float* vp = g_v + gbase + (size_t)row * DM + c4;
        float4 qv = *(const float4*)qp;
        float4 kv = *(const float4*)kp;
        float4 vv = *(const float4*)vp;
        *(uint4*)&Qs[row * QP + c4] =
            make_uint4(f2tf32(qv.x), f2tf32(qv.y), f2tf32(qv.z), f2tf32(qv.w));
        *(uint4*)&Ks[row * QP + c4] =
            make_uint4(f2tf32(kv.x), f2tf32(kv.y), f2tf32(kv.z), f2tf32(kv.w));
        *(uint4*)&Vs[row * QP + c4] =
            make_uint4(f2tf32(vv.x), f2tf32(vv.y), f2tf32(vv.z), f2tf32(vv.w));
    }
    __syncthreads();

    float sacc[4][4][4];
#pragma unroll
    for (int mt = 0; mt < 4; mt++)
#pragma unroll
        for (int nt = 0; nt < 4; nt++)
#pragma unroll
            for (int r = 0; r < 4; r++) sacc[mt][nt][r] = 0.f;

#pragma unroll
    for (int ks = 0; ks < 8; ks++) {
        uint32_t a[4][4], b[4][2];
#pragma unroll
        for (int mt = 0; mt < 4; mt++) {
            int ar = (wm * 64 + mt * 16 + g) * QP + ks * 8 + tt;
            a[mt][0] = Qs[ar];
            a[mt][1] = Qs[ar + 8 * QP];
            a[mt][2] = Qs[ar + 4];
            a[mt][3] = Qs[ar + 8 * QP + 4];
        }
#pragma unroll
        for (int nt = 0; nt < 4; nt++) {
            int br = (wn * 32 + nt * 8 + g) * QP + ks * 8 + tt;
            b[nt][0] = Ks[br];
            b[nt][1] = Ks[br + 4];
        }
#pragma unroll
        for (int mt = 0; mt < 4; mt++)
#pragma unroll
            for (int nt = 0; nt < 4; nt++)
                mma8(sacc[mt][nt], a[mt], b[nt]);
    }
    __syncthreads();

    const float scale = 0.125f;
#pragma unroll
    for (int mt = 0; mt < 4; mt++) {
        int r0 = (wm * 64 + mt * 16 + g) * SP;
        int r1 = r0 + 8 * SP;
#pragma unroll
        for (int nt = 0; nt < 4; nt++) {
            int c = wn * 32 + nt * 8 + tt * 2;
            Ss[r0 + c]     = sacc[mt][nt][0] * scale;
            Ss[r0 + c + 1] = sacc[mt][nt][1] * scale;
            Ss[r1 + c]     = sacc[mt][nt][2] * scale;
            Ss[r1 + c + 1] = sacc[mt][nt][3] * scale;
        }
    }
    __syncthreads();

    for (int r = warp * 16; r < warp * 16 + 16; r++) {
        float* srow = Ss + r * SP;
        float v0 = srow[lane];
        float v1 = srow[lane + 32];
        float v2 = srow[lane + 64];
        float v3 = srow[lane + 96];
        float mx = fmaxf(fmaxf(v0, v1), fmaxf(v2, v3));
#pragma unroll
        for (int o = 16; o > 0; o >>= 1)
            mx = fmaxf(mx, __shfl_xor_sync(0xffffffffu, mx, o));
        float e0 = fexp(v0 - mx);
        float e1 = fexp(v1 - mx);
        float e2 = fexp(v2 - mx);
        float e3 = fexp(v3 - mx);
        float s = e0 + e1 + e2 + e3;
#pragma unroll
        for (int o = 16; o > 0; o >>= 1)
            s += __shfl_xor_sync(0xffffffffu, s, o);
        float inv = 1.f / s;
        uint32_t* urow = (uint32_t*)srow;
        urow[lane]      = f2tf32(e0 * inv);
        urow[lane + 32] = f2tf32(e1 * inv);
        urow[lane + 64] = f2tf32(e2 * inv);
        urow[lane + 96] = f2tf32(e3 * inv);
    }
    __syncthreads();

    float oacc[4][2][4];
#pragma unroll
    for (int mt = 0; mt < 4; mt++)
#pragma unroll
        for (int nt = 0; nt < 2; nt++)
#pragma unroll
            for (int r = 0; r < 4; r++) oacc[mt][nt][r] = 0.f;

#pragma unroll
    for (int ks = 0; ks < 16; ks++) {
        uint32_t a[4][4], b[2][2];
#pragma unroll
        for (int mt = 0; mt < 4; mt++) {
            int ar = (wm * 64 + mt * 16 + g) * SP + ks * 8 + tt;
            a[mt][0] = Ssu[ar];
            a[mt][1] = Ssu[ar + 8 * SP];
            a[mt][2] = Ssu[ar + 4];
            a[mt][3] = Ssu[ar + 8 * SP + 4];
        }
#pragma unroll
        for (int nt = 0; nt < 2; nt++) {
            int br = (ks * 8 + tt) * QP + wn * 16 + nt * 8 + g;
            b[nt][0] = Vs[br];
            b[nt][1] = Vs[br + 4 * QP];
        }
#pragma unroll
        for (int mt = 0; mt < 4; mt++)
#pragma unroll
            for (int nt = 0; nt < 2; nt++)
                mma8(oacc[mt][nt], a[mt], b[nt]);
    }

#pragma unroll
    for (int mt = 0; mt < 4; mt++) {
        const int row0 = wm * 64 + mt * 16 + g;
#pragma unroll
        for (int nt = 0; nt < 2; nt++) {
            const int c = wn * 16 + nt * 8 + tt * 2;
            float* p0 = g_ao + gbase + (size_t)row0 * DM + c;
            float* p1 = g_ao + gbase + (size_t)(row0 + 8) * DM + c;
            *(float2*)p0 = make_float2(oacc[mt][nt][0], oacc[mt][nt][1]);
            *(float2*)p1 = make_float2(oacc[mt][nt][2], oacc[mt][nt][3]);
        }
    }
}

// ---------------------------------------------------------------------------
// kernel_launch
// ---------------------------------------------------------------------------
extern "C" void kernel_launch(void* const* d_in, const int* in_sizes, int n_in,
                              void* d_out, int out_size)
{
    const float* x  = (const float*)d_in[0];
    const float* Wq = (const float*)d_in[1];
    const float* bq = (const float*)d_in[2];
    const float* Wk = (const float*)d_in[3];
    const float* bk = (const float*)d_in[4];
    const float* Wv = (const float*)d_in[5];
    const float* bv = (const float*)d_in[6];
    const float* Wp = (const float*)d_in[7];
    const float* bp = (const float*)d_in[8];
    float* out = (float*)d_out;

    void *pq, *pk, *pv, *pao;
    cudaGetSymbolAddress(&pq,  g_q);
    cudaGetSymbolAddress(&pk,  g_k);
    cudaGetSymbolAddress(&pv,  g_v);
    cudaGetSymbolAddress(&pao, g_ao);
    float* gq  = (float*)pq;
    float* gk  = (float*)pk;
    float* gv  = (float*)pv;
    float* gao = (float*)pao;

    cudaFuncSetAttribute(gemm_tc,
                         cudaFuncAttributeMaxDynamicSharedMemorySize, GEMM_SMEM_BYTES);
    cudaFuncSetAttribute(attn_kernel,
                         cudaFuncAttributeMaxDynamicSharedMemorySize, ATTN_SMEM_BYTES);

    dim3 gblk(256);
    dim3 ggrid(DM / 128, MTOT / 128);   // (4, 256)

    gemm_tc<<<ggrid, gblk, GEMM_SMEM_BYTES>>>(x, Wq, bq, gq);
    gemm_tc<<<ggrid, gblk, GEMM_SMEM_BYTES>>>(x, Wk, bk, gk);
    gemm_tc<<<ggrid, gblk, GEMM_SMEM_BYTES>>>(x, Wv, bv, gv);

    dim3 agrid(HEADS, NWIN);            // (8, 256)
    attn_kernel<<<agrid, gblk, ATTN_SMEM_BYTES>>>();

    gemm_tc<<<ggrid, gblk, GEMM_SMEM_BYTES>>>(gao, Wp, bp, out);
}

// round 12
// speedup vs baseline: 1.1575x; 1.1575x over previous
#include <cuda_runtime.h>
#include <cstdint>

// Problem constants
#define MTOT   32768      // B*S
#define DM     512        // d_model
#define HEADS  8
#define HD     64
#define WSZ    128
#define NWIN   256

// ---------------------------------------------------------------------------
// Scratch (device globals; no runtime allocation allowed)
// ---------------------------------------------------------------------------
__device__ float g_q [MTOT * DM];
__device__ float g_k [MTOT * DM];
__device__ float g_v [MTOT * DM];
__device__ float g_ao[MTOT * DM];

// ---------------------------------------------------------------------------
// helpers
// ---------------------------------------------------------------------------
__device__ __forceinline__ uint32_t f2tf32(float f) {
    uint32_t r;
    asm("cvt.rna.tf32.f32 %0, %1;" : "=r"(r) : "f"(f));
    return r;
}

// mma.sync m16n8k8 tf32 (baseline PTX; valid on plain sm_103 target)
__device__ __forceinline__ void mma8(float* d, const uint32_t* a, const uint32_t* b) {
    asm volatile(
        "mma.sync.aligned.m16n8k8.row.col.f32.tf32.tf32.f32 "
        "{%0,%1,%2,%3}, {%4,%5,%6,%7}, {%8,%9}, {%0,%1,%2,%3};"
        : "+f"(d[0]), "+f"(d[1]), "+f"(d[2]), "+f"(d[3])
        : "r"(a[0]), "r"(a[1]), "r"(a[2]), "r"(a[3]), "r"(b[0]), "r"(b[1]));
}

// Fast exp on FMA/ALU pipes only (no MUFU, no CVT). x <= 0 here.
__device__ __forceinline__ float fexp(float x) {
    float y = x * 1.44269504088896f;
    float t = y + 12582912.f;
    float n = t - 12582912.f;
    float f = y - n;
    float p = 0.00133335581f;
    p = fmaf(p, f, 0.00961812910f);
    p = fmaf(p, f, 0.05550410866f);
    p = fmaf(p, f, 0.24022650696f);
    p = fmaf(p, f, 0.69314718056f);
    p = fmaf(p, f, 1.0f);
    int ni = __float_as_int(t) - 0x4B400000;
    float s = __int_as_float((ni + 127) << 23);
    return p * s;
}

// ---------------------------------------------------------------------------
// tf32 tensor GEMM v3: C = A*W^T + bias
// Round-5 skeleton (single-buffered smem, 2 syncs/chunk, register prefetch,
// NO occupancy cap) + paired-XOR smem layout:
//   word(r, c) = r*40 + (c>>3)*8 + ( (2*(c&3) + ((c>>2)&1)) ^ (2*(r&3)) )
// Fragment pairs (tt, tt+4) are adjacent -> LDS.64 fragment loads; both
// staging STS.32 and compute LDS.64 are bank-conflict-free (verified:
// staging banks 8(row+q)+b+(2j^2(row&3)); compute banks 8g+(2tt^2(g&3))).
// ---------------------------------------------------------------------------
#define KC      32
#define NCH     (DM / KC)        // 16
#define PITCHW  40

__device__ __forceinline__ void stage_frag(uint32_t* buf, int srow, int scolq,
                                           float4 v) {
    int base = srow * PITCHW + (scolq >> 1) * 8 + (scolq & 1);
    int e = 2 * (srow & 3);
    buf[base + (0 ^ e)] = f2tf32(v.x);
    buf[base + (2 ^ e)] = f2tf32(v.y);
    buf[base + (4 ^ e)] = f2tf32(v.z);
    buf[base + (6 ^ e)] = f2tf32(v.w);
}

__global__ __launch_bounds__(256) void gemm_tc(
    const float* __restrict__ A, const float* __restrict__ W,
    const float* __restrict__ bias, float* __restrict__ C)
{
    __shared__ uint32_t As[128 * PITCHW];   // 20 KB
    __shared__ uint32_t Ws[128 * PITCHW];   // 20 KB

    const int t    = threadIdx.x;
    const int warp = t >> 5;
    const int lane = t & 31;
    const int wm   = warp >> 2;
    const int wn   = warp & 3;
    const int g    = lane >> 2;
    const int tt   = lane & 3;
    const int m0   = blockIdx.y * 128;
    const int n0   = blockIdx.x * 128;
    const int esw  = 2 * (g & 3);

    int srow[4], scolq[4];
#pragma unroll
    for (int e = 0; e < 4; e++) {
        int f = e * 256 + t;
        srow[e]  = f >> 3;
        scolq[e] = f & 7;
    }

    float acc[4][4][4];
#pragma unroll
    for (int mt = 0; mt < 4; mt++)
#pragma unroll
        for (int nt = 0; nt < 4; nt++)
#pragma unroll
            for (int r = 0; r < 4; r++) acc[mt][nt][r] = 0.f;

    // prefetch chunk 0
    float4 pa[4], pw[4];
#pragma unroll
    for (int e = 0; e < 4; e++) {
        pa[e] = *(const float4*)(A + (size_t)(m0 + srow[e]) * DM + scolq[e] * 4);
        pw[e] = *(const float4*)(W + (size_t)(n0 + srow[e]) * DM + scolq[e] * 4);
    }

    for (int ch = 0; ch < NCH; ch++) {
        // store prefetched chunk (tf32 RN conversion)
#pragma unroll
        for (int e = 0; e < 4; e++) {
            stage_frag(As, srow[e], scolq[e], pa[e]);
            stage_frag(Ws, srow[e], scolq[e], pw[e]);
        }
        __syncthreads();

        // prefetch next chunk (overlaps compute)
        if (ch + 1 < NCH) {
            const int ccol = (ch + 1) * KC;
#pragma unroll
            for (int e = 0; e < 4; e++) {
                pa[e] = *(const float4*)(A + (size_t)(m0 + srow[e]) * DM + ccol + scolq[e] * 4);
                pw[e] = *(const float4*)(W + (size_t)(n0 + srow[e]) * DM + ccol + scolq[e] * 4);
            }
        }

        // compute 4 k-steps (paired LDS.64 fragment loads)
#pragma unroll
        for (int ks = 0; ks < 4; ks++) {
            const int kb = ks * 8 + ((2 * tt) ^ esw);
            uint32_t a[4][4], b[4][2];
#pragma unroll
            for (int mt = 0; mt < 4; mt++) {
                int ra = (wm * 64 + mt * 16 + g) * PITCHW + kb;
                uint2 lo = *(const uint2*)&As[ra];                 // (a0, a2)
                uint2 hi = *(const uint2*)&As[ra + 8 * PITCHW];    // (a1, a3)
                a[mt][0] = lo.x; a[mt][1] = hi.x;
                a[mt][2] = lo.y; a[mt][3] = hi.y;
            }
#pragma unroll
            for (int nt = 0; nt < 4; nt++) {
                int rb = (wn * 32 + nt * 8 + g) * PITCHW + kb;
                uint2 bb = *(const uint2*)&Ws[rb];
                b[nt][0] = bb.x; b[nt][1] = bb.y;
            }
#pragma unroll
            for (int mt = 0; mt < 4; mt++)
#pragma unroll
                for (int nt = 0; nt < 4; nt++)
                    mma8(acc[mt][nt], a[mt], b[nt]);
        }
        __syncthreads();
    }

    // epilogue: bias add + store
#pragma unroll
    for (int mt = 0; mt < 4; mt++) {
        const int row0 = m0 + wm * 64 + mt * 16 + g;
#pragma unroll
        for (int nt = 0; nt < 4; nt++) {
            const int c = n0 + wn * 32 + nt * 8 + tt * 2;
            float b0 = bias[c], b1 = bias[c + 1];
            float* p0 = C + (size_t)row0 * DM + c;
            float* p1 = C + (size_t)(row0 + 8) * DM + c;
            *(float2*)p0 = make_float2(acc[mt][nt][0] + b0, acc[mt][nt][1] + b1);
            *(float2*)p1 = make_float2(acc[mt][nt][2] + b0, acc[mt][nt][3] + b1);
        }
    }
}

// ---------------------------------------------------------------------------
// Windowed attention (unchanged, validated 136.6us): tensor matmuls +
// FMA-pipe softmax. One CTA per (window, head).
// ---------------------------------------------------------------------------
#define QP 68
#define SP 132
#define ATTN_SMEM_BYTES ((2 * 128 * QP + 128 * QP) * 4)   // 104448

__global__ __launch_bounds__(256, 2) void attn_kernel()
{
    extern __shared__ float smf[];
    float*    Qsf = smf;
    float*    Ksf = smf + 128 * QP;
    uint32_t* Qs  = (uint32_t*)Qsf;
    uint32_t* Ks  = (uint32_t*)Ksf;
    float*    Ss  = smf;                       // aliases Qs+Ks
    uint32_t* Ssu = (uint32_t*)Ss;
    float*    Vsf = smf + 2 * 128 * QP;
    uint32_t* Vs  = (uint32_t*)Vsf;

    const int h    = blockIdx.x;
    const int wdw  = blockIdx.y;
    const int t    = threadIdx.x;
    const int warp = t >> 5;
    const int lane = t & 31;
    const int wm   = warp >> 2;
    const int wn   = warp & 3;
    const int g    = lane >> 2;
    const int tt   = lane & 3;

    const size_t gbase = (size_t)wdw * WSZ * DM + (size_t)h * HD;

#pragma unroll
    for (int it = 0; it < 8; it++) {
        int f   = it * 256 + t;
        int row = f >> 4;
        int c4  = (f & 15) << 2;
        const float* qp = g_q + gbase + (size_t)row * DM + c4;
        const float* kp = g_k + gbase + (size_t)row * DM + c4;
        const float* vp = g_v + gbase + (size_t)row * DM + c4;
        float4 qv = *(const float4*)qp;
        float4 kv = *(const float4*)kp;
        float4 vv = *(const float4*)vp;
        *(uint4*)&Qs[row * QP + c4] =
            make_uint4(f2tf32(qv.x), f2tf32(qv.y), f2tf32(qv.z), f2tf32(qv.w));
        *(uint4*)&Ks[row * QP + c4] =
            make_uint4(f2tf32(kv.x), f2tf32(kv.y), f2tf32(kv.z), f2tf32(kv.w));
        *(uint4*)&Vs[row * QP + c4] =
            make_uint4(f2tf32(vv.x), f2tf32(vv.y), f2tf32(vv.z), f2tf32(vv.w));
    }
    __syncthreads();

    float sacc[4][4][4];
#pragma unroll
    for (int mt = 0; mt < 4; mt++)
#pragma unroll
        for (int nt = 0; nt < 4; nt++)
#pragma unroll
            for (int r = 0; r < 4; r++) sacc[mt][nt][r] = 0.f;

#pragma unroll
    for (int ks = 0; ks < 8; ks++) {
        uint32_t a[4][4], b[4][2];
#pragma unroll
        for (int mt = 0; mt < 4; mt++) {
            int ar = (wm * 64 + mt * 16 + g) * QP + ks * 8 + tt;
            a[mt][0] = Qs[ar];
            a[mt][1] = Qs[ar + 8 * QP];
            a[mt][2] = Qs[ar + 4];
            a[mt][3] = Qs[ar + 8 * QP + 4];
        }
#pragma unroll
        for (int nt = 0; nt < 4; nt++) {
            int br = (wn * 32 + nt * 8 + g) * QP + ks * 8 + tt;
            b[nt][0] = Ks[br];
            b[nt][1] = Ks[br + 4];
        }
#pragma unroll
        for (int mt = 0; mt < 4; mt++)
#pragma unroll
            for (int nt = 0; nt < 4; nt++)
                mma8(sacc[mt][nt], a[mt], b[nt]);
    }
    __syncthreads();

    const float scale = 0.125f;
#pragma unroll
    for (int mt = 0; mt < 4; mt++) {
        int r0 = (wm * 64 + mt * 16 + g) * SP;
        int r1 = r0 + 8 * SP;
#pragma unroll
        for (int nt = 0; nt < 4; nt++) {
            int c = wn * 32 + nt * 8 + tt * 2;
            Ss[r0 + c]     = sacc[mt][nt][0] * scale;
            Ss[r0 + c + 1] = sacc[mt][nt][1] * scale;
            Ss[r1 + c]     = sacc[mt][nt][2] * scale;
            Ss[r1 + c + 1] = sacc[mt][nt][3] * scale;
        }
    }
    __syncthreads();

    for (int r = warp * 16; r < warp * 16 + 16; r++) {
        float* srow = Ss + r * SP;
        float v0 = srow[lane];
        float v1 = srow[lane + 32];
        float v2 = srow[lane + 64];
        float v3 = srow[lane + 96];
        float mx = fmaxf(fmaxf(v0, v1), fmaxf(v2, v3));
#pragma unroll
        for (int o = 16; o > 0; o >>= 1)
            mx = fmaxf(mx, __shfl_xor_sync(0xffffffffu, mx, o));
        float e0 = fexp(v0 - mx);
        float e1 = fexp(v1 - mx);
        float e2 = fexp(v2 - mx);
        float e3 = fexp(v3 - mx);
        float s = e0 + e1 + e2 + e3;
#pragma unroll
        for (int o = 16; o > 0; o >>= 1)
            s += __shfl_xor_sync(0xffffffffu, s, o);
        float inv = 1.f / s;
        uint32_t* urow = (uint32_t*)srow;
        urow[lane]      = f2tf32(e0 * inv);
        urow[lane + 32] = f2tf32(e1 * inv);
        urow[lane + 64] = f2tf32(e2 * inv);
        urow[lane + 96] = f2tf32(e3 * inv);
    }
    __syncthreads();

    float oacc[4][2][4];
#pragma unroll
    for (int mt = 0; mt < 4; mt++)
#pragma unroll
        for (int nt = 0; nt < 2; nt++)
#pragma unroll
            for (int r = 0; r < 4; r++) oacc[mt][nt][r] = 0.f;

#pragma unroll
    for (int ks = 0; ks < 16; ks++) {
        uint32_t a[4][4], b[2][2];
#pragma unroll
        for (int mt = 0; mt < 4; mt++) {
            int ar = (wm * 64 + mt * 16 + g) * SP + ks * 8 + tt;
            a[mt][0] = Ssu[ar];
            a[mt][1] = Ssu[ar + 8 * SP];
            a[mt][2] = Ssu[ar + 4];
            a[mt][3] = Ssu[ar + 8 * SP + 4];
        }
#pragma unroll
        for (int nt = 0; nt < 2; nt++) {
            int br = (ks * 8 + tt) * QP + wn * 16 + nt * 8 + g;
            b[nt][0] = Vs[br];
            b[nt][1] = Vs[br + 4 * QP];
        }
#pragma unroll
        for (int mt = 0; mt < 4; mt++)
#pragma unroll
            for (int nt = 0; nt < 2; nt++)
                mma8(oacc[mt][nt], a[mt], b[nt]);
    }

#pragma unroll
    for (int mt = 0; mt < 4; mt++) {
        const int row0 = wm * 64 + mt * 16 + g;
#pragma unroll
        for (int nt = 0; nt < 2; nt++) {
            const int c = wn * 16 + nt * 8 + tt * 2;
            float* p0 = g_ao + gbase + (size_t)row0 * DM + c;
            float* p1 = g_ao + gbase + (size_t)(row0 + 8) * DM + c;
            *(float2*)p0 = make_float2(oacc[mt][nt][0], oacc[mt][nt][1]);
            *(float2*)p1 = make_float2(oacc[mt][nt][2], oacc[mt][nt][3]);
        }
    }
}

// ---------------------------------------------------------------------------
// kernel_launch
// ---------------------------------------------------------------------------
extern "C" void kernel_launch(void* const* d_in, const int* in_sizes, int n_in,
                              void* d_out, int out_size)
{
    const float* x  = (const float*)d_in[0];
    const float* Wq = (const float*)d_in[1];
    const float* bq = (const float*)d_in[2];
    const float* Wk = (const float*)d_in[3];
    const float* bk = (const float*)d_in[4];
    const float* Wv = (const float*)d_in[5];
    const float* bv = (const float*)d_in[6];
    const float* Wp = (const float*)d_in[7];
    const float* bp = (const float*)d_in[8];
    float* out = (float*)d_out;

    void *pq, *pk, *pv, *pao;
    cudaGetSymbolAddress(&pq,  g_q);
    cudaGetSymbolAddress(&pk,  g_k);
    cudaGetSymbolAddress(&pv,  g_v);
    cudaGetSymbolAddress(&pao, g_ao);
    float* gq  = (float*)pq;
    float* gk  = (float*)pk;
    float* gv  = (float*)pv;
    float* gao = (float*)pao;

    cudaFuncSetAttribute(attn_kernel,
                         cudaFuncAttributeMaxDynamicSharedMemorySize, ATTN_SMEM_BYTES);

    dim3 gblk(256);
    dim3 ggrid(DM / 128, MTOT / 128);   // (4, 256)

    gemm_tc<<<ggrid, gblk>>>(x, Wq, bq, gq);
    gemm_tc<<<ggrid, gblk>>>(x, Wk, bk, gk);
    gemm_tc<<<ggrid, gblk>>>(x, Wv, bv, gv);

    dim3 agrid(HEADS, NWIN);            // (8, 256)
    attn_kernel<<<agrid, gblk, ATTN_SMEM_BYTES>>>();

    gemm_tc<<<ggrid, gblk>>>(gao, Wp, bp, out);
}

// round 13
// speedup vs baseline: 1.4546x; 1.2566x over previous
#include <cuda_runtime.h>
#include <cstdint>

// Problem constants
#define MTOT   32768      // B*S
#define DM     512        // d_model
#define HEADS  8
#define HD     64
#define WSZ    128
#define NWIN   256

// ---------------------------------------------------------------------------
// Scratch (device globals; no runtime allocation allowed)
// ---------------------------------------------------------------------------
__device__ float g_q [MTOT * DM];
__device__ float g_k [MTOT * DM];
__device__ float g_v [MTOT * DM];
__device__ float g_ao[MTOT * DM];
__device__ float g_xr[MTOT * DM];     // x pre-rounded to tf32
__device__ float g_wr[4][DM * DM];    // Wq,Wk,Wv,Wp pre-rounded to tf32

// ---------------------------------------------------------------------------
// helpers
// ---------------------------------------------------------------------------
__device__ __forceinline__ uint32_t f2tf32(float f) {
    uint32_t r;
    asm("cvt.rna.tf32.f32 %0, %1;" : "=r"(r) : "f"(f));
    return r;
}

// mma.sync m16n8k8 tf32 (baseline PTX; valid on plain sm_103 target)
__device__ __forceinline__ void mma8(float* d, const uint32_t* a, const uint32_t* b) {
    asm volatile(
        "mma.sync.aligned.m16n8k8.row.col.f32.tf32.tf32.f32 "
        "{%0,%1,%2,%3}, {%4,%5,%6,%7}, {%8,%9}, {%0,%1,%2,%3};"
        : "+f"(d[0]), "+f"(d[1]), "+f"(d[2]), "+f"(d[3])
        : "r"(a[0]), "r"(a[1]), "r"(a[2]), "r"(a[3]), "r"(b[0]), "r"(b[1]));
}

// Fast exp on FMA/ALU pipes only (no MUFU, no CVT). x <= 0 here.
__device__ __forceinline__ float fexp(float x) {
    float y = x * 1.44269504088896f;
    float t = y + 12582912.f;
    float n = t - 12582912.f;
    float f = y - n;
    float p = 0.00133335581f;
    p = fmaf(p, f, 0.00961812910f);
    p = fmaf(p, f, 0.05550410866f);
    p = fmaf(p, f, 0.24022650696f);
    p = fmaf(p, f, 0.69314718056f);
    p = fmaf(p, f, 1.0f);
    int ni = __float_as_int(t) - 0x4B400000;
    float s = __int_as_float((ni + 127) << 23);
    return p * s;
}

#define CP_ASYNC16(dst_u32, src_ptr) \
    asm volatile("cp.async.cg.shared.global [%0], [%1], 16;" \
                 :: "r"(dst_u32), "l"(src_ptr))
#define CP_COMMIT() asm volatile("cp.async.commit_group;" ::: "memory")
#define CP_WAIT1()  asm volatile("cp.async.wait_group 1;" ::: "memory")

// ---------------------------------------------------------------------------
// Pre-pass: round fp32 -> tf32 bits (stored as float)
// ---------------------------------------------------------------------------
__global__ __launch_bounds__(256) void cvt_tf32(const float* __restrict__ in,
                                                float* __restrict__ out, int n4)
{
    int i = blockIdx.x * 256 + threadIdx.x;
    if (i < n4) {
        float4 v = ((const float4*)in)[i];
        float4 o;
        o.x = __uint_as_float(f2tf32(v.x));
        o.y = __uint_as_float(f2tf32(v.y));
        o.z = __uint_as_float(f2tf32(v.z));
        o.w = __uint_as_float(f2tf32(v.w));
        ((float4*)out)[i] = o;
    }
}

// ---------------------------------------------------------------------------
// tf32 tensor GEMM v4: C = A*W^T + bias. Inputs PRE-ROUNDED to tf32.
// CTA 128x128, 8 warps (2m x 4n), K chunks of 32, 3-stage cp.async pipeline.
// Smem per tensor per stage: 128 rows x 32 words, SW128 swizzle at 16B
// granularity: 16B-chunk j of row r stored at chunk (j ^ (r&7)).
// ---------------------------------------------------------------------------
#define KC    32
#define NCH   (DM / KC)          // 16
#define NST   3
#define TILEW (128 * 32)         // 4096 words = 16 KB
#define GEMM_SMEM_BYTES (NST * 2 * TILEW * 4)   // 98304

__global__ __launch_bounds__(256, 2) void gemm_tc(
    const float* __restrict__ A, const float* __restrict__ W,
    const float* __restrict__ bias, float* __restrict__ C)
{
    extern __shared__ uint32_t smw[];
    const uint32_t sb = (uint32_t)__cvta_generic_to_shared(smw);

    const int t    = threadIdx.x;
    const int warp = t >> 5;
    const int lane = t & 31;
    const int wm   = warp >> 2;
    const int wn   = warp & 3;
    const int g    = lane >> 2;
    const int tt   = lane & 3;
    const int m0   = blockIdx.y * 128;
    const int n0   = blockIdx.x * 128;

    // staging coords: f = e*256+t ; r = f>>3 ; j = f&7 (16B chunk)
    int sr[4], sj[4], sdw[4];          // sdw: smem word offset within tile
#pragma unroll
    for (int e = 0; e < 4; e++) {
        int f  = e * 256 + t;
        sr[e]  = f >> 3;
        sj[e]  = f & 7;
        sdw[e] = sr[e] * 32 + (sj[e] ^ (sr[e] & 7)) * 4;
    }

    float acc[4][4][4];
#pragma unroll
    for (int mt = 0; mt < 4; mt++)
#pragma unroll
        for (int nt = 0; nt < 4; nt++)
#pragma unroll
            for (int r = 0; r < 4; r++) acc[mt][nt][r] = 0.f;

    // prologue: issue stages 0 and 1
#pragma unroll
    for (int s = 0; s < 2; s++) {
        uint32_t ba = sb + (s * 2 * TILEW) * 4;
        uint32_t bw = ba + TILEW * 4;
        const int ccol = s * KC;
#pragma unroll
        for (int e = 0; e < 4; e++) {
            CP_ASYNC16(ba + sdw[e] * 4, A + (size_t)(m0 + sr[e]) * DM + ccol + sj[e] * 4);
            CP_ASYNC16(bw + sdw[e] * 4, W + (size_t)(n0 + sr[e]) * DM + ccol + sj[e] * 4);
        }
        CP_COMMIT();
    }

    for (int ch = 0; ch < NCH; ch++) {
        CP_WAIT1();
        __syncthreads();

        // issue stage ch+2 (buffer last read at iter ch-1, fenced by sync)
        if (ch + 2 < NCH) {
            const int s = (ch + 2) % NST;
            uint32_t ba = sb + (s * 2 * TILEW) * 4;
            uint32_t bw = ba + TILEW * 4;
            const int ccol = (ch + 2) * KC;
#pragma unroll
            for (int e = 0; e < 4; e++) {
                CP_ASYNC16(ba + sdw[e] * 4, A + (size_t)(m0 + sr[e]) * DM + ccol + sj[e] * 4);
                CP_ASYNC16(bw + sdw[e] * 4, W + (size_t)(n0 + sr[e]) * DM + ccol + sj[e] * 4);
            }
        }
        CP_COMMIT();

        // compute from buffer ch%NST
        const uint32_t* As = smw + (ch % NST) * 2 * TILEW;
        const uint32_t* Ws = As + TILEW;
#pragma unroll
        for (int ks = 0; ks < 4; ks++) {
            const int c0 = ((2 * ks) ^ g) * 4 + tt;       // chunk for cols tt
            const int c1 = ((2 * ks + 1) ^ g) * 4 + tt;   // chunk for cols tt+4
            uint32_t a[4][4], b[4][2];
#pragma unroll
            for (int mt = 0; mt < 4; mt++) {
                int R = (wm * 64 + mt * 16 + g) * 32;
                a[mt][0] = As[R + c0];
                a[mt][1] = As[R + 8 * 32 + c0];
                a[mt][2] = As[R + c1];
                a[mt][3] = As[R + 8 * 32 + c1];
            }
#pragma unroll
            for (int nt = 0; nt < 4; nt++) {
                int R = (wn * 32 + nt * 8 + g) * 32;
                b[nt][0] = Ws[R + c0];
                b[nt][1] = Ws[R + c1];
            }
#pragma unroll
            for (int mt = 0; mt < 4; mt++)
#pragma unroll
                for (int nt = 0; nt < 4; nt++)
                    mma8(acc[mt][nt], a[mt], b[nt]);
        }
    }

    // epilogue: bias add + store
#pragma unroll
    for (int mt = 0; mt < 4; mt++) {
        const int row0 = m0 + wm * 64 + mt * 16 + g;
#pragma unroll
        for (int nt = 0; nt < 4; nt++) {
            const int c = n0 + wn * 32 + nt * 8 + tt * 2;
            float b0 = bias[c], b1 = bias[c + 1];
            float* p0 = C + (size_t)row0 * DM + c;
            float* p1 = C + (size_t)(row0 + 8) * DM + c;
            *(float2*)p0 = make_float2(acc[mt][nt][0] + b0, acc[mt][nt][1] + b1);
            *(float2*)p1 = make_float2(acc[mt][nt][2] + b0, acc[mt][nt][3] + b1);
        }
    }
}

// ---------------------------------------------------------------------------
// Windowed attention (round-7 core, validated 136us). O is written
// tf32-ROUNDED so the projection GEMM can stage it with raw byte copies.
// ---------------------------------------------------------------------------
#define QP 68
#define SP 132
#define ATTN_SMEM_BYTES ((2 * 128 * QP + 128 * QP) * 4)   // 104448

__global__ __launch_bounds__(256, 2) void attn_kernel()
{
    extern __shared__ float smf[];
    float*    Qsf = smf;
    float*    Ksf = smf + 128 * QP;
    uint32_t* Qs  = (uint32_t*)Qsf;
    uint32_t* Ks  = (uint32_t*)Ksf;
    float*    Ss  = smf;                       // aliases Qs+Ks
    uint32_t* Ssu = (uint32_t*)Ss;
    float*    Vsf = smf + 2 * 128 * QP;
    uint32_t* Vs  = (uint32_t*)Vsf;

    const int h    = blockIdx.x;
    const int wdw  = blockIdx.y;
    const int t    = threadIdx.x;
    const int warp = t >> 5;
    const int lane = t & 31;
    const int wm   = warp >> 2;
    const int wn   = warp & 3;
    const int g    = lane >> 2;
    const int tt   = lane & 3;

    const size_t gbase = (size_t)wdw * WSZ * DM + (size_t)h * HD;

#pragma unroll
    for (int it = 0; it < 8; it++) {
        int f   = it * 256 + t;
        int row = f >> 4;
        int c4  = (f & 15) << 2;
        const float* qp = g_q + gbase + (size_t)row * DM + c4;
        const float* kp = g_k + gbase + (size_t)row * DM + c4;
        const float* vp = g_v + gbase + (size_t)row * DM + c4;
        float4 qv = *(const float4*)qp;
        float4 kv = *(const float4*)kp;
        float4 vv = *(const float4*)vp;
        *(uint4*)&Qs[row * QP + c4] =
            make_uint4(f2tf32(qv.x), f2tf32(qv.y), f2tf32(qv.z), f2tf32(qv.w));
        *(uint4*)&Ks[row * QP + c4] =
            make_uint4(f2tf32(kv.x), f2tf32(kv.y), f2tf32(kv.z), f2tf32(kv.w));
        *(uint4*)&Vs[row * QP + c4] =
            make_uint4(f2tf32(vv.x), f2tf32(vv.y), f2tf32(vv.z), f2tf32(vv.w));
    }
    __syncthreads();

    float sacc[4][4][4];
#pragma unroll
    for (int mt = 0; mt < 4; mt++)
#pragma unroll
        for (int nt = 0; nt < 4; nt++)
#pragma unroll
            for (int r = 0; r < 4; r++) sacc[mt][nt][r] = 0.f;

#pragma unroll
    for (int ks = 0; ks < 8; ks++) {
        uint32_t a[4][4], b[4][2];
#pragma unroll
        for (int mt = 0; mt < 4; mt++) {
            int ar = (wm * 64 + mt * 16 + g) * QP + ks * 8 + tt;
            a[mt][0] = Qs[ar];
            a[mt][1] = Qs[ar + 8 * QP];
            a[mt][2] = Qs[ar + 4];
            a[mt][3] = Qs[ar + 8 * QP + 4];
        }
#pragma unroll
        for (int nt = 0; nt < 4; nt++) {
            int br = (wn * 32 + nt * 8 + g) * QP + ks * 8 + tt;
            b[nt][0] = Ks[br];
            b[nt][1] = Ks[br + 4];
        }
#pragma unroll
        for (int mt = 0; mt < 4; mt++)
#pragma unroll
            for (int nt = 0; nt < 4; nt++)
                mma8(sacc[mt][nt], a[mt], b[nt]);
    }
    __syncthreads();

    const float scale = 0.125f;
#pragma unroll
    for (int mt = 0; mt < 4; mt++) {
        int r0 = (wm * 64 + mt * 16 + g) * SP;
        int r1 = r0 + 8 * SP;
#pragma unroll
        for (int nt = 0; nt < 4; nt++) {
            int c = wn * 32 + nt * 8 + tt * 2;
            Ss[r0 + c]     = sacc[mt][nt][0] * scale;
            Ss[r0 + c + 1] = sacc[mt][nt][1] * scale;
            Ss[r1 + c]     = sacc[mt][nt][2] * scale;
            Ss[r1 + c + 1] = sacc[mt][nt][3] * scale;
        }
    }
    __syncthreads();

    for (int r = warp * 16; r < warp * 16 + 16; r++) {
        float* srow = Ss + r * SP;
        float v0 = srow[lane];
        float v1 = srow[lane + 32];
        float v2 = srow[lane + 64];
        float v3 = srow[lane + 96];
        float mx = fmaxf(fmaxf(v0, v1), fmaxf(v2, v3));
#pragma unroll
        for (int o = 16; o > 0; o >>= 1)
            mx = fmaxf(mx, __shfl_xor_sync(0xffffffffu, mx, o));
        float e0 = fexp(v0 - mx);
        float e1 = fexp(v1 - mx);
        float e2 = fexp(v2 - mx);
        float e3 = fexp(v3 - mx);
        float s = e0 + e1 + e2 + e3;
#pragma unroll
        for (int o = 16; o > 0; o >>= 1)
            s += __shfl_xor_sync(0xffffffffu, s, o);
        float inv = 1.f / s;
        uint32_t* urow = (uint32_t*)srow;
        urow[lane]      = f2tf32(e0 * inv);
        urow[lane + 32] = f2tf32(e1 * inv);
        urow[lane + 64] = f2tf32(e2 * inv);
        urow[lane + 96] = f2tf32(e3 * inv);
    }
    __syncthreads();

    float oacc[4][2][4];
#pragma unroll
    for (int mt = 0; mt < 4; mt++)
#pragma unroll
        for (int nt = 0; nt < 2; nt++)
#pragma unroll
            for (int r = 0; r < 4; r++) oacc[mt][nt][r] = 0.f;

#pragma unroll
    for (int ks = 0; ks < 16; ks++) {
        uint32_t a[4][4], b[2][2];
#pragma unroll
        for (int mt = 0; mt < 4; mt++) {
            int ar = (wm * 64 + mt * 16 + g) * SP + ks * 8 + tt;
            a[mt][0] = Ssu[ar];
            a[mt][1] = Ssu[ar + 8 * SP];
            a[mt][2] = Ssu[ar + 4];
            a[mt][3] = Ssu[ar + 8 * SP + 4];
        }
#pragma unroll
        for (int nt = 0; nt < 2; nt++) {
            int br = (ks * 8 + tt) * QP + wn * 16 + nt * 8 + g;
            b[nt][0] = Vs[br];
            b[nt][1] = Vs[br + 4 * QP];
        }
#pragma unroll
        for (int mt = 0; mt < 4; mt++)
#pragma unroll
            for (int nt = 0; nt < 2; nt++)
                mma8(oacc[mt][nt], a[mt], b[nt]);
    }

    // write O, pre-rounded to tf32 for the projection GEMM
#pragma unroll
    for (int mt = 0; mt < 4; mt++) {
        const int row0 = wm * 64 + mt * 16 + g;
#pragma unroll
        for (int nt = 0; nt < 2; nt++) {
            const int c = wn * 16 + nt * 8 + tt * 2;
            float* p0 = g_ao + gbase + (size_t)row0 * DM + c;
            float* p1 = g_ao + gbase + (size_t)(row0 + 8) * DM + c;
            *(float2*)p0 = make_float2(__uint_as_float(f2tf32(oacc[mt][nt][0])),
                                       __uint_as_float(f2tf32(oacc[mt][nt][1])));
            *(float2*)p1 = make_float2(__uint_as_float(f2tf32(oacc[mt][nt][2])),
                                       __uint_as_float(f2tf32(oacc[mt][nt][3])));
        }
    }
}

// ---------------------------------------------------------------------------
// kernel_launch
// ---------------------------------------------------------------------------
extern "C" void kernel_launch(void* const* d_in, const int* in_sizes, int n_in,
                              void* d_out, int out_size)
{
    const float* x  = (const float*)d_in[0];
    const float* Wq = (const float*)d_in[1];
    const float* bq = (const float*)d_in[2];
    const float* Wk = (const float*)d_in[3];
    const float* bk = (const float*)d_in[4];
    const float* Wv = (const float*)d_in[5];
    const float* bv = (const float*)d_in[6];
    const float* Wp = (const float*)d_in[7];
    const float* bp = (const float*)d_in[8];
    float* out = (float*)d_out;

    void *pq, *pk, *pv, *pao, *pxr, *pwr;
    cudaGetSymbolAddress(&pq,  g_q);
    cudaGetSymbolAddress(&pk,  g_k);
    cudaGetSymbolAddress(&pv,  g_v);
    cudaGetSymbolAddress(&pao, g_ao);
    cudaGetSymbolAddress(&pxr, g_xr);
    cudaGetSymbolAddress(&pwr, g_wr);
    float* gq  = (float*)pq;
    float* gk  = (float*)pk;
    float* gv  = (float*)pv;
    float* gao = (float*)pao;
    float* gxr = (float*)pxr;
    float* gwr = (float*)pwr;

    cudaFuncSetAttribute(gemm_tc,
                         cudaFuncAttributeMaxDynamicSharedMemorySize, GEMM_SMEM_BYTES);
    cudaFuncSetAttribute(attn_kernel,
                         cudaFuncAttributeMaxDynamicSharedMemorySize, ATTN_SMEM_BYTES);

    // pre-pass: round x and weights to tf32
    const int NX4 = MTOT * DM / 4;     // 4194304
    const int NW4 = DM * DM / 4;       // 65536
    cvt_tf32<<<(NX4 + 255) / 256, 256>>>(x,  gxr, NX4);
    cvt_tf32<<<(NW4 + 255) / 256, 256>>>(Wq, gwr + 0 * DM * DM, NW4);
    cvt_tf32<<<(NW4 + 255) / 256, 256>>>(Wk, gwr + 1 * DM * DM, NW4);
    cvt_tf32<<<(NW4 + 255) / 256, 256>>>(Wv, gwr + 2 * DM * DM, NW4);
    cvt_tf32<<<(NW4 + 255) / 256, 256>>>(Wp, gwr + 3 * DM * DM, NW4);

    dim3 gblk(256);
    dim3 ggrid(DM / 128, MTOT / 128);   // (4, 256)

    gemm_tc<<<ggrid, gblk, GEMM_SMEM_BYTES>>>(gxr, gwr + 0 * DM * DM, bq, gq);
    gemm_tc<<<ggrid, gblk, GEMM_SMEM_BYTES>>>(gxr, gwr + 1 * DM * DM, bk, gk);
    gemm_tc<<<ggrid, gblk, GEMM_SMEM_BYTES>>>(gxr, gwr + 2 * DM * DM, bv, gv);

    dim3 agrid(HEADS, NWIN);            // (8, 256)
    attn_kernel<<<agrid, gblk, ATTN_SMEM_BYTES>>>();

    gemm_tc<<<ggrid, gblk, GEMM_SMEM_BYTES>>>(gao, gwr + 3 * DM * DM, bp, out);
}

// round 14
// speedup vs baseline: 1.4767x; 1.0152x over previous
#include <cuda_runtime.h>
#include <cstdint>

// Problem constants
#define MTOT   32768      // B*S
#define DM     512        // d_model
#define HEADS  8
#define HD     64
#define WSZ    128
#define NWIN   256

// ---------------------------------------------------------------------------
// Scratch (device globals; no runtime allocation allowed)
// ---------------------------------------------------------------------------
__device__ float g_q [MTOT * DM];
__device__ float g_k [MTOT * DM];
__device__ float g_v [MTOT * DM];
__device__ float g_ao[MTOT * DM];
__device__ float g_xr[MTOT * DM];     // x pre-rounded to tf32
__device__ float g_wr[4][DM * DM];    // Wq,Wk,Wv,Wp pre-rounded (contiguous)

// ---------------------------------------------------------------------------
// helpers
// ---------------------------------------------------------------------------
__device__ __forceinline__ uint32_t f2tf32(float f) {
    uint32_t r;
    asm("cvt.rna.tf32.f32 %0, %1;" : "=r"(r) : "f"(f));
    return r;
}
__device__ __forceinline__ float f2tf32f(float f) {
    return __uint_as_float(f2tf32(f));
}

// mma.sync m16n8k8 tf32 (baseline PTX; valid on plain sm_103 target)
__device__ __forceinline__ void mma8(float* d, const uint32_t* a, const uint32_t* b) {
    asm volatile(
        "mma.sync.aligned.m16n8k8.row.col.f32.tf32.tf32.f32 "
        "{%0,%1,%2,%3}, {%4,%5,%6,%7}, {%8,%9}, {%0,%1,%2,%3};"
        : "+f"(d[0]), "+f"(d[1]), "+f"(d[2]), "+f"(d[3])
        : "r"(a[0]), "r"(a[1]), "r"(a[2]), "r"(a[3]), "r"(b[0]), "r"(b[1]));
}

// Fast exp on FMA/ALU pipes only (no MUFU, no CVT). x <= 0 here.
__device__ __forceinline__ float fexp(float x) {
    float y = x * 1.44269504088896f;
    float t = y + 12582912.f;
    float n = t - 12582912.f;
    float f = y - n;
    float p = 0.00133335581f;
    p = fmaf(p, f, 0.00961812910f);
    p = fmaf(p, f, 0.05550410866f);
    p = fmaf(p, f, 0.24022650696f);
    p = fmaf(p, f, 0.69314718056f);
    p = fmaf(p, f, 1.0f);
    int ni = __float_as_int(t) - 0x4B400000;
    float s = __int_as_float((ni + 127) << 23);
    return p * s;
}

#define CP_ASYNC16(dst_u32, src_ptr) \
    asm volatile("cp.async.cg.shared.global [%0], [%1], 16;" \
                 :: "r"(dst_u32), "l"(src_ptr))
#define CP_COMMIT() asm volatile("cp.async.commit_group;" ::: "memory")
#define CP_WAIT1()  asm volatile("cp.async.wait_group 1;" ::: "memory")
#define CP_WAIT0()  asm volatile("cp.async.wait_group 0;" ::: "memory")

// ---------------------------------------------------------------------------
// Pre-pass: round fp32 -> tf32 bits (stored as float)
// ---------------------------------------------------------------------------
__global__ __launch_bounds__(256) void cvt_tf32(const float* __restrict__ in,
                                                float* __restrict__ out, int n4)
{
    int i = blockIdx.x * 256 + threadIdx.x;
    if (i < n4) {
        float4 v = ((const float4*)in)[i];
        float4 o;
        o.x = f2tf32f(v.x);
        o.y = f2tf32f(v.y);
        o.z = f2tf32f(v.z);
        o.w = f2tf32f(v.w);
        ((float4*)out)[i] = o;
    }
}

// ---------------------------------------------------------------------------
// tf32 tensor GEMM v5: C_sel = A*W^T + bias_sel. Inputs PRE-ROUNDED to tf32.
// W packed [gridDim.x*32 rows x 512]; CTA selects output tensor/bias by
// sel = n0>>9 (supports fused QKV: grid.x=12 -> sel 0..2; proj: grid.x=4 -> 0).
// 3-stage cp.async pipeline, SW128 16B-chunk swizzle (j ^ (r&7)).
// round_out: epilogue stores tf32-rounded values (for QKV -> attention).
// ---------------------------------------------------------------------------
#define KC    32
#define NCH   (DM / KC)          // 16
#define NST   3
#define TILEW (128 * 32)         // 4096 words = 16 KB
#define GEMM_SMEM_BYTES (NST * 2 * TILEW * 4)   // 98304

__global__ __launch_bounds__(256, 2) void gemm_tc(
    const float* __restrict__ A, const float* __restrict__ W,
    const float* __restrict__ bias0, const float* __restrict__ bias1,
    const float* __restrict__ bias2,
    float* __restrict__ C0, float* __restrict__ C1, float* __restrict__ C2,
    int round_out)
{
    extern __shared__ uint32_t smw[];
    const uint32_t sb = (uint32_t)__cvta_generic_to_shared(smw);

    const int t    = threadIdx.x;
    const int warp = t >> 5;
    const int lane = t & 31;
    const int wm   = warp >> 2;
    const int wn   = warp & 3;
    const int g    = lane >> 2;
    const int tt   = lane & 3;
    const int m0   = blockIdx.y * 128;
    const int n0   = blockIdx.x * 128;     // global row into packed W

    int sr[4], sj[4], sdw[4];
#pragma unroll
    for (int e = 0; e < 4; e++) {
        int f  = e * 256 + t;
        sr[e]  = f >> 3;
        sj[e]  = f & 7;
        sdw[e] = sr[e] * 32 + (sj[e] ^ (sr[e] & 7)) * 4;
    }

    float acc[4][4][4];
#pragma unroll
    for (int mt = 0; mt < 4; mt++)
#pragma unroll
        for (int nt = 0; nt < 4; nt++)
#pragma unroll
            for (int r = 0; r < 4; r++) acc[mt][nt][r] = 0.f;

    // prologue: issue stages 0 and 1
#pragma unroll
    for (int s = 0; s < 2; s++) {
        uint32_t ba = sb + (s * 2 * TILEW) * 4;
        uint32_t bw = ba + TILEW * 4;
        const int ccol = s * KC;
#pragma unroll
        for (int e = 0; e < 4; e++) {
            CP_ASYNC16(ba + sdw[e] * 4, A + (size_t)(m0 + sr[e]) * DM + ccol + sj[e] * 4);
            CP_ASYNC16(bw + sdw[e] * 4, W + (size_t)(n0 + sr[e]) * DM + ccol + sj[e] * 4);
        }
        CP_COMMIT();
    }

    for (int ch = 0; ch < NCH; ch++) {
        CP_WAIT1();
        __syncthreads();

        if (ch + 2 < NCH) {
            const int s = (ch + 2) % NST;
            uint32_t ba = sb + (s * 2 * TILEW) * 4;
            uint32_t bw = ba + TILEW * 4;
            const int ccol = (ch + 2) * KC;
#pragma unroll
            for (int e = 0; e < 4; e++) {
                CP_ASYNC16(ba + sdw[e] * 4, A + (size_t)(m0 + sr[e]) * DM + ccol + sj[e] * 4);
                CP_ASYNC16(bw + sdw[e] * 4, W + (size_t)(n0 + sr[e]) * DM + ccol + sj[e] * 4);
            }
        }
        CP_COMMIT();

        const uint32_t* As = smw + (ch % NST) * 2 * TILEW;
        const uint32_t* Ws = As + TILEW;
#pragma unroll
        for (int ks = 0; ks < 4; ks++) {
            const int c0 = ((2 * ks) ^ g) * 4 + tt;
            const int c1 = ((2 * ks + 1) ^ g) * 4 + tt;
            uint32_t a[4][4], b[4][2];
#pragma unroll
            for (int mt = 0; mt < 4; mt++) {
                int R = (wm * 64 + mt * 16 + g) * 32;
                a[mt][0] = As[R + c0];
                a[mt][1] = As[R + 8 * 32 + c0];
                a[mt][2] = As[R + c1];
                a[mt][3] = As[R + 8 * 32 + c1];
            }
#pragma unroll
            for (int nt = 0; nt < 4; nt++) {
                int R = (wn * 32 + nt * 8 + g) * 32;
                b[nt][0] = Ws[R + c0];
                b[nt][1] = Ws[R + c1];
            }
#pragma unroll
            for (int mt = 0; mt < 4; mt++)
#pragma unroll
                for (int nt = 0; nt < 4; nt++)
                    mma8(acc[mt][nt], a[mt], b[nt]);
        }
    }

    // epilogue: select output tensor/bias by n0, bias add, optional rounding
    const int sel  = n0 >> 9;
    const int nloc = n0 & 511;
    const float* bias = (sel == 0) ? bias0 : (sel == 1) ? bias1 : bias2;
    float* C = (sel == 0) ? C0 : (sel == 1) ? C1 : C2;

#pragma unroll
    for (int mt = 0; mt < 4; mt++) {
        const int row0 = m0 + wm * 64 + mt * 16 + g;
#pragma unroll
        for (int nt = 0; nt < 4; nt++) {
            const int c = nloc + wn * 32 + nt * 8 + tt * 2;
            float b0 = bias[c], b1 = bias[c + 1];
            float v0 = acc[mt][nt][0] + b0, v1 = acc[mt][nt][1] + b1;
            float v2 = acc[mt][nt][2] + b0, v3 = acc[mt][nt][3] + b1;
            if (round_out) {
                v0 = f2tf32f(v0); v1 = f2tf32f(v1);
                v2 = f2tf32f(v2); v3 = f2tf32f(v3);
            }
            float* p0 = C + (size_t)row0 * DM + c;
            float* p1 = C + (size_t)(row0 + 8) * DM + c;
            *(float2*)p0 = make_float2(v0, v1);
            *(float2*)p1 = make_float2(v2, v3);
        }
    }
}

// ---------------------------------------------------------------------------
// Windowed attention v3: inputs pre-rounded to tf32 (no CVT in staging).
// V staged via cp.async, overlapping S-compute + softmax.
// ---------------------------------------------------------------------------
#define QP 68
#define SP 132
#define ATTN_SMEM_BYTES ((2 * 128 * QP + 128 * QP) * 4)   // 104448

__global__ __launch_bounds__(256, 2) void attn_kernel()
{
    extern __shared__ float smf[];
    float*    Qsf = smf;
    float*    Ksf = smf + 128 * QP;
    uint32_t* Qs  = (uint32_t*)Qsf;
    uint32_t* Ks  = (uint32_t*)Ksf;
    float*    Ss  = smf;                       // aliases Qs+Ks
    uint32_t* Ssu = (uint32_t*)Ss;
    float*    Vsf = smf + 2 * 128 * QP;
    uint32_t* Vs  = (uint32_t*)Vsf;
    const uint32_t sbV = (uint32_t)__cvta_generic_to_shared(Vsf);

    const int h    = blockIdx.x;
    const int wdw  = blockIdx.y;
    const int t    = threadIdx.x;
    const int warp = t >> 5;
    const int lane = t & 31;
    const int wm   = warp >> 2;
    const int wn   = warp & 3;
    const int g    = lane >> 2;
    const int tt   = lane & 3;

    const size_t gbase = (size_t)wdw * WSZ * DM + (size_t)h * HD;

    // ---- V via cp.async (arrives during S-compute/softmax) ----
#pragma unroll
    for (int it = 0; it < 8; it++) {
        int f   = it * 256 + t;
        int row = f >> 4;
        int c4  = (f & 15) << 2;
        CP_ASYNC16(sbV + (row * QP + c4) * 4, g_v + gbase + (size_t)row * DM + c4);
    }
    CP_COMMIT();

    // ---- Q, K staged as raw bytes (already tf32-rounded by GEMM) ----
#pragma unroll
    for (int it = 0; it < 8; it++) {
        int f   = it * 256 + t;
        int row = f >> 4;
        int c4  = (f & 15) << 2;
        *(float4*)&Qsf[row * QP + c4] = *(const float4*)(g_q + gbase + (size_t)row * DM + c4);
        *(float4*)&Ksf[row * QP + c4] = *(const float4*)(g_k + gbase + (size_t)row * DM + c4);
    }
    __syncthreads();

    // ---- phase 1: S = Q K^T ----
    float sacc[4][4][4];
#pragma unroll
    for (int mt = 0; mt < 4; mt++)
#pragma unroll
        for (int nt = 0; nt < 4; nt++)
#pragma unroll
            for (int r = 0; r < 4; r++) sacc[mt][nt][r] = 0.f;

#pragma unroll
    for (int ks = 0; ks < 8; ks++) {
        uint32_t a[4][4], b[4][2];
#pragma unroll
        for (int mt = 0; mt < 4; mt++) {
            int ar = (wm * 64 + mt * 16 + g) * QP + ks * 8 + tt;
            a[mt][0] = Qs[ar];
            a[mt][1] = Qs[ar + 8 * QP];
            a[mt][2] = Qs[ar + 4];
            a[mt][3] = Qs[ar + 8 * QP + 4];
        }
#pragma unroll
        for (int nt = 0; nt < 4; nt++) {
            int br = (wn * 32 + nt * 8 + g) * QP + ks * 8 + tt;
            b[nt][0] = Ks[br];
            b[nt][1] = Ks[br + 4];
        }
#pragma unroll
        for (int mt = 0; mt < 4; mt++)
#pragma unroll
            for (int nt = 0; nt < 4; nt++)
                mma8(sacc[mt][nt], a[mt], b[nt]);
    }
    __syncthreads();

    const float scale = 0.125f;
#pragma unroll
    for (int mt = 0; mt < 4; mt++) {
        int r0 = (wm * 64 + mt * 16 + g) * SP;
        int r1 = r0 + 8 * SP;
#pragma unroll
        for (int nt = 0; nt < 4; nt++) {
            int c = wn * 32 + nt * 8 + tt * 2;
            Ss[r0 + c]     = sacc[mt][nt][0] * scale;
            Ss[r0 + c + 1] = sacc[mt][nt][1] * scale;
            Ss[r1 + c]     = sacc[mt][nt][2] * scale;
            Ss[r1 + c + 1] = sacc[mt][nt][3] * scale;
        }
    }
    __syncthreads();

    // ---- softmax (poly exp), write P as tf32 ----
    for (int r = warp * 16; r < warp * 16 + 16; r++) {
        float* srow = Ss + r * SP;
        float v0 = srow[lane];
        float v1 = srow[lane + 32];
        float v2 = srow[lane + 64];
        float v3 = srow[lane + 96];
        float mx = fmaxf(fmaxf(v0, v1), fmaxf(v2, v3));
#pragma unroll
        for (int o = 16; o > 0; o >>= 1)
            mx = fmaxf(mx, __shfl_xor_sync(0xffffffffu, mx, o));
        float e0 = fexp(v0 - mx);
        float e1 = fexp(v1 - mx);
        float e2 = fexp(v2 - mx);
        float e3 = fexp(v3 - mx);
        float s = e0 + e1 + e2 + e3;
#pragma unroll
        for (int o = 16; o > 0; o >>= 1)
            s += __shfl_xor_sync(0xffffffffu, s, o);
        float inv = 1.f / s;
        uint32_t* urow = (uint32_t*)srow;
        urow[lane]      = f2tf32(e0 * inv);
        urow[lane + 32] = f2tf32(e1 * inv);
        urow[lane + 64] = f2tf32(e2 * inv);
        urow[lane + 96] = f2tf32(e3 * inv);
    }
    CP_WAIT0();          // V fully arrived (overlapped with S + softmax)
    __syncthreads();

    // ---- phase 2: O = P V ----
    float oacc[4][2][4];
#pragma unroll
    for (int mt = 0; mt < 4; mt++)
#pragma unroll
        for (int nt = 0; nt < 2; nt++)
#pragma unroll
            for (int r = 0; r < 4; r++) oacc[mt][nt][r] = 0.f;

#pragma unroll
    for (int ks = 0; ks < 16; ks++) {
        uint32_t a[4][4], b[2][2];
#pragma unroll
        for (int mt = 0; mt < 4; mt++) {
            int ar = (wm * 64 + mt * 16 + g) * SP + ks * 8 + tt;
            a[mt][0] = Ssu[ar];
            a[mt][1] = Ssu[ar + 8 * SP];
            a[mt][2] = Ssu[ar + 4];
            a[mt][3] = Ssu[ar + 8 * SP + 4];
        }
#pragma unroll
        for (int nt = 0; nt < 2; nt++) {
            int br = (ks * 8 + tt) * QP + wn * 16 + nt * 8 + g;
            b[nt][0] = Vs[br];
            b[nt][1] = Vs[br + 4 * QP];
        }
#pragma unroll
        for (int mt = 0; mt < 4; mt++)
#pragma unroll
            for (int nt = 0; nt < 2; nt++)
                mma8(oacc[mt][nt], a[mt], b[nt]);
    }

    // write O, pre-rounded to tf32 for the projection GEMM
#pragma unroll
    for (int mt = 0; mt < 4; mt++) {
        const int row0 = wm * 64 + mt * 16 + g;
#pragma unroll
        for (int nt = 0; nt < 2; nt++) {
            const int c = wn * 16 + nt * 8 + tt * 2;
            float* p0 = g_ao + gbase + (size_t)row0 * DM + c;
            float* p1 = g_ao + gbase + (size_t)(row0 + 8) * DM + c;
            *(float2*)p0 = make_float2(f2tf32f(oacc[mt][nt][0]), f2tf32f(oacc[mt][nt][1]));
            *(float2*)p1 = make_float2(f2tf32f(oacc[mt][nt][2]), f2tf32f(oacc[mt][nt][3]));
        }
    }
}

// ---------------------------------------------------------------------------
// kernel_launch
// ---------------------------------------------------------------------------
extern "C" void kernel_launch(void* const* d_in, const int* in_sizes, int n_in,
                              void* d_out, int out_size)
{
    const float* x  = (const float*)d_in[0];
    const float* Wq = (const float*)d_in[1];
    const float* bq = (const float*)d_in[2];
    const float* Wk = (const float*)d_in[3];
    const float* bk = (const float*)d_in[4];
    const float* Wv = (const float*)d_in[5];
    const float* bv = (const float*)d_in[6];
    const float* Wp = (const float*)d_in[7];
    const float* bp = (const float*)d_in[8];
    float* out = (float*)d_out;

    void *pq, *pk, *pv, *pao, *pxr, *pwr;
    cudaGetSymbolAddress(&pq,  g_q);
    cudaGetSymbolAddress(&pk,  g_k);
    cudaGetSymbolAddress(&pv,  g_v);
    cudaGetSymbolAddress(&pao, g_ao);
    cudaGetSymbolAddress(&pxr, g_xr);
    cudaGetSymbolAddress(&pwr, g_wr);
    float* gq  = (float*)pq;
    float* gk  = (float*)pk;
    float* gv  = (float*)pv;
    float* gao = (float*)pao;
    float* gxr = (float*)pxr;
    float* gwr = (float*)pwr;

    cudaFuncSetAttribute(gemm_tc,
                         cudaFuncAttributeMaxDynamicSharedMemorySize, GEMM_SMEM_BYTES);
    cudaFuncSetAttribute(attn_kernel,
                         cudaFuncAttributeMaxDynamicSharedMemorySize, ATTN_SMEM_BYTES);

    // pre-pass: round x and weights to tf32 (weights packed contiguously)
    const int NX4 = MTOT * DM / 4;
    const int NW4 = DM * DM / 4;
    cvt_tf32<<<(NX4 + 255) / 256, 256>>>(x,  gxr, NX4);
    cvt_tf32<<<(NW4 + 255) / 256, 256>>>(Wq, gwr + 0 * DM * DM, NW4);
    cvt_tf32<<<(NW4 + 255) / 256, 256>>>(Wk, gwr + 1 * DM * DM, NW4);
    cvt_tf32<<<(NW4 + 255) / 256, 256>>>(Wv, gwr + 2 * DM * DM, NW4);
    cvt_tf32<<<(NW4 + 255) / 256, 256>>>(Wp, gwr + 3 * DM * DM, NW4);

    dim3 gblk(256);

    // fused QKV projection: packed W rows 0..1535, outputs rounded to tf32
    dim3 qkvgrid(3 * DM / 128, MTOT / 128);   // (12, 256)
    gemm_tc<<<qkvgrid, gblk, GEMM_SMEM_BYTES>>>(gxr, gwr, bq, bk, bv,
                                                gq, gk, gv, 1);

    dim3 agrid(HEADS, NWIN);                  // (8, 256)
    attn_kernel<<<agrid, gblk, ATTN_SMEM_BYTES>>>();

    // output projection: NOT rounded (final fp32 output)
    dim3 pgrid(DM / 128, MTOT / 128);         // (4, 256)
    gemm_tc<<<pgrid, gblk, GEMM_SMEM_BYTES>>>(gao, gwr + 3 * DM * DM, bp, bp, bp,
                                              out, out, out, 0);
}

// round 15
// speedup vs baseline: 1.5388x; 1.0420x over previous
#include <cuda_runtime.h>
#include <cstdint>

// Problem constants
#define MTOT   32768      // B*S
#define DM     512        // d_model
#define HEADS  8
#define HD     64
#define WSZ    128
#define NWIN   256

// ---------------------------------------------------------------------------
// Scratch (device globals; no runtime allocation allowed)
// ---------------------------------------------------------------------------
__device__ float g_q [MTOT * DM];     // head-major [win][head][128][64]
__device__ float g_k [MTOT * DM];     // head-major
__device__ float g_v [MTOT * DM];     // head-major
__device__ float g_ao[MTOT * DM];     // flat [row][512]
__device__ float g_xr[MTOT * DM];     // x pre-rounded to tf32
__device__ float g_wr[4][DM * DM];    // Wq,Wk,Wv,Wp pre-rounded (contiguous)

// ---------------------------------------------------------------------------
// helpers
// ---------------------------------------------------------------------------
__device__ __forceinline__ uint32_t f2tf32(float f) {
    uint32_t r;
    asm("cvt.rna.tf32.f32 %0, %1;" : "=r"(r) : "f"(f));
    return r;
}
__device__ __forceinline__ float f2tf32f(float f) {
    return __uint_as_float(f2tf32(f));
}

// mma.sync m16n8k8 tf32 (baseline PTX; valid on plain sm_103 target)
__device__ __forceinline__ void mma8(float* d, const uint32_t* a, const uint32_t* b) {
    asm volatile(
        "mma.sync.aligned.m16n8k8.row.col.f32.tf32.tf32.f32 "
        "{%0,%1,%2,%3}, {%4,%5,%6,%7}, {%8,%9}, {%0,%1,%2,%3};"
        : "+f"(d[0]), "+f"(d[1]), "+f"(d[2]), "+f"(d[3])
        : "r"(a[0]), "r"(a[1]), "r"(a[2]), "r"(a[3]), "r"(b[0]), "r"(b[1]));
}

// Fast exp on FMA/ALU pipes only (no MUFU, no CVT). x <= 0 here.
__device__ __forceinline__ float fexp(float x) {
    float y = x * 1.44269504088896f;
    float t = y + 12582912.f;
    float n = t - 12582912.f;
    float f = y - n;
    float p = 0.00133335581f;
    p = fmaf(p, f, 0.00961812910f);
    p = fmaf(p, f, 0.05550410866f);
    p = fmaf(p, f, 0.24022650696f);
    p = fmaf(p, f, 0.69314718056f);
    p = fmaf(p, f, 1.0f);
    int ni = __float_as_int(t) - 0x4B400000;
    float s = __int_as_float((ni + 127) << 23);
    return p * s;
}

#define CP_ASYNC16(dst_u32, src_ptr) \
    asm volatile("cp.async.cg.shared.global [%0], [%1], 16;" \
                 :: "r"(dst_u32), "l"(src_ptr))
#define CP_COMMIT() asm volatile("cp.async.commit_group;" ::: "memory")
#define CP_WAIT1()  asm volatile("cp.async.wait_group 1;" ::: "memory")
#define CP_WAIT0()  asm volatile("cp.async.wait_group 0;" ::: "memory")

// ---------------------------------------------------------------------------
// Pre-pass kernels: round fp32 -> tf32 bits (stored as float)
// ---------------------------------------------------------------------------
__global__ __launch_bounds__(256) void cvt_tf32(const float* __restrict__ in,
                                                float* __restrict__ out, int n4)
{
    int i = blockIdx.x * 256 + threadIdx.x;
    if (i < n4) {
        float4 v = ((const float4*)in)[i];
        ((float4*)out)[i] = make_float4(f2tf32f(v.x), f2tf32f(v.y),
                                        f2tf32f(v.z), f2tf32f(v.w));
    }
}

// all four weight matrices in one launch; blockIdx.y selects the matrix
__global__ __launch_bounds__(256) void cvt_w4(
    const float* __restrict__ w0, const float* __restrict__ w1,
    const float* __restrict__ w2, const float* __restrict__ w3,
    float* __restrict__ out)
{
    const int which = blockIdx.y;
    const float* in = (which == 0) ? w0 : (which == 1) ? w1 : (which == 2) ? w2 : w3;
    const int n4 = DM * DM / 4;
    int i = blockIdx.x * 256 + threadIdx.x;
    if (i < n4) {
        float4 v = ((const float4*)in)[i];
        ((float4*)(out + (size_t)which * DM * DM))[i] =
            make_float4(f2tf32f(v.x), f2tf32f(v.y), f2tf32f(v.z), f2tf32f(v.w));
    }
}

// ---------------------------------------------------------------------------
// tf32 tensor GEMM v6: C_sel = A*W^T + bias_sel. Inputs PRE-ROUNDED to tf32.
// 3-stage cp.async pipeline, SW128 16B-chunk swizzle (j ^ (r&7)).
// round_out=1: tf32-rounded output in HEAD-MAJOR layout [win][head][128][64]
//              (QKV -> attention). round_out=0: flat [row][512] fp32 (proj).
// ---------------------------------------------------------------------------
#define KC    32
#define NCH   (DM / KC)          // 16
#define NST   3
#define TILEW (128 * 32)         // 4096 words = 16 KB
#define GEMM_SMEM_BYTES (NST * 2 * TILEW * 4)   // 98304

__global__ __launch_bounds__(256, 2) void gemm_tc(
    const float* __restrict__ A, const float* __restrict__ W,
    const float* __restrict__ bias0, const float* __restrict__ bias1,
    const float* __restrict__ bias2,
    float* __restrict__ C0, float* __restrict__ C1, float* __restrict__ C2,
    int round_out)
{
    extern __shared__ uint32_t smw[];
    const uint32_t sb = (uint32_t)__cvta_generic_to_shared(smw);

    const int t    = threadIdx.x;
    const int warp = t >> 5;
    const int lane = t & 31;
    const int wm   = warp >> 2;
    const int wn   = warp & 3;
    const int g    = lane >> 2;
    const int tt   = lane & 3;
    const int m0   = blockIdx.y * 128;
    const int n0   = blockIdx.x * 128;     // global row into packed W

    int sr[4], sj[4], sdw[4];
#pragma unroll
    for (int e = 0; e < 4; e++) {
        int f  = e * 256 + t;
        sr[e]  = f >> 3;
        sj[e]  = f & 7;
        sdw[e] = sr[e] * 32 + (sj[e] ^ (sr[e] & 7)) * 4;
    }

    float acc[4][4][4];
#pragma unroll
    for (int mt = 0; mt < 4; mt++)
#pragma unroll
        for (int nt = 0; nt < 4; nt++)
#pragma unroll
            for (int r = 0; r < 4; r++) acc[mt][nt][r] = 0.f;

#pragma unroll
    for (int s = 0; s < 2; s++) {
        uint32_t ba = sb + (s * 2 * TILEW) * 4;
        uint32_t bw = ba + TILEW * 4;
        const int ccol = s * KC;
#pragma unroll
        for (int e = 0; e < 4; e++) {
            CP_ASYNC16(ba + sdw[e] * 4, A + (size_t)(m0 + sr[e]) * DM + ccol + sj[e] * 4);
            CP_ASYNC16(bw + sdw[e] * 4, W + (size_t)(n0 + sr[e]) * DM + ccol + sj[e] * 4);
        }
        CP_COMMIT();
    }

    for (int ch = 0; ch < NCH; ch++) {
        CP_WAIT1();
        __syncthreads();

        if (ch + 2 < NCH) {
            const int s = (ch + 2) % NST;
            uint32_t ba = sb + (s * 2 * TILEW) * 4;
            uint32_t bw = ba + TILEW * 4;
            const int ccol = (ch + 2) * KC;
#pragma unroll
            for (int e = 0; e < 4; e++) {
                CP_ASYNC16(ba + sdw[e] * 4, A + (size_t)(m0 + sr[e]) * DM + ccol + sj[e] * 4);
                CP_ASYNC16(bw + sdw[e] * 4, W + (size_t)(n0 + sr[e]) * DM + ccol + sj[e] * 4);
            }
        }
        CP_COMMIT();

        const uint32_t* As = smw + (ch % NST) * 2 * TILEW;
        const uint32_t* Ws = As + TILEW;
#pragma unroll
        for (int ks = 0; ks < 4; ks++) {
            const int c0 = ((2 * ks) ^ g) * 4 + tt;
            const int c1 = ((2 * ks + 1) ^ g) * 4 + tt;
            uint32_t a[4][4], b[4][2];
#pragma unroll
            for (int mt = 0; mt < 4; mt++) {
                int R = (wm * 64 + mt * 16 + g) * 32;
                a[mt][0] = As[R + c0];
                a[mt][1] = As[R + 8 * 32 + c0];
                a[mt][2] = As[R + c1];
                a[mt][3] = As[R + 8 * 32 + c1];
            }
#pragma unroll
            for (int nt = 0; nt < 4; nt++) {
                int R = (wn * 32 + nt * 8 + g) * 32;
                b[nt][0] = Ws[R + c0];
                b[nt][1] = Ws[R + c1];
            }
#pragma unroll
            for (int mt = 0; mt < 4; mt++)
#pragma unroll
                for (int nt = 0; nt < 4; nt++)
                    mma8(acc[mt][nt], a[mt], b[nt]);
        }
    }

    // epilogue
    const int sel  = n0 >> 9;
    const int nloc = n0 & 511;
    const float* bias = (sel == 0) ? bias0 : (sel == 1) ? bias1 : bias2;
    float* C = (sel == 0) ? C0 : (sel == 1) ? C1 : C2;

#pragma unroll
    for (int mt = 0; mt < 4; mt++) {
        const int row0 = m0 + wm * 64 + mt * 16 + g;   // row0 and row0+8 share a window
#pragma unroll
        for (int nt = 0; nt < 4; nt++) {
            const int c = nloc + wn * 32 + nt * 8 + tt * 2;
            float b0 = bias[c], b1 = bias[c + 1];
            float v0 = acc[mt][nt][0] + b0, v1 = acc[mt][nt][1] + b1;
            float v2 = acc[mt][nt][2] + b0, v3 = acc[mt][nt][3] + b1;
            if (round_out) {
                // head-major: [win][head][wrow][c64]
                const int head = c >> 6, c64 = c & 63;
                const int win  = row0 >> 7, wrow = row0 & 127;
                float* base = C + (((size_t)(win * HEADS + head) * WSZ + wrow) * HD + c64);
                *(float2*)base            = make_float2(f2tf32f(v0), f2tf32f(v1));
                *(float2*)(base + 8 * HD) = make_float2(f2tf32f(v2), f2tf32f(v3));
            } else {
                float* p0 = C + (size_t)row0 * DM + c;
                float* p1 = C + (size_t)(row0 + 8) * DM + c;
                *(float2*)p0 = make_float2(v0, v1);
                *(float2*)p1 = make_float2(v2, v3);
            }
        }
    }
}

// ---------------------------------------------------------------------------
// Windowed attention v4: head-major QKV inputs, ALL staging via cp.async.
// Group 0 = Q+K (waited before S), group 1 = V (waited before P*V).
// ---------------------------------------------------------------------------
#define QP 68
#define SP 132
#define ATTN_SMEM_BYTES ((2 * 128 * QP + 128 * QP) * 4)   // 104448

__global__ __launch_bounds__(256, 2) void attn_kernel()
{
    extern __shared__ float smf[];
    float*    Qsf = smf;
    float*    Ksf = smf + 128 * QP;
    uint32_t* Qs  = (uint32_t*)Qsf;
    uint32_t* Ks  = (uint32_t*)Ksf;
    float*    Ss  = smf;                       // aliases Qs+Ks
    uint32_t* Ssu = (uint32_t*)Ss;
    float*    Vsf = smf + 2 * 128 * QP;
    uint32_t* Vs  = (uint32_t*)Vsf;
    const uint32_t sbQ = (uint32_t)__cvta_generic_to_shared(Qsf);
    const uint32_t sbK = (uint32_t)__cvta_generic_to_shared(Ksf);
    const uint32_t sbV = (uint32_t)__cvta_generic_to_shared(Vsf);

    const int h    = blockIdx.x;
    const int wdw  = blockIdx.y;
    const int t    = threadIdx.x;
    const int warp = t >> 5;
    const int lane = t & 31;
    const int wm   = warp >> 2;
    const int wn   = warp & 3;
    const int g    = lane >> 2;
    const int tt   = lane & 3;

    // head-major block base: [win][head][128][64]
    const size_t hbase = ((size_t)(wdw * HEADS + h)) * WSZ * HD;
    // flat base for O
    const size_t obase = (size_t)wdw * WSZ * DM + (size_t)h * HD;

    // ---- group 0: Q + K (contiguous 32KB blocks, 16B cp.async) ----
#pragma unroll
    for (int it = 0; it < 8; it++) {
        int f   = it * 256 + t;
        int row = f >> 4;
        int c4  = (f & 15) << 2;
        CP_ASYNC16(sbQ + (row * QP + c4) * 4, g_q + hbase + row * HD + c4);
        CP_ASYNC16(sbK + (row * QP + c4) * 4, g_k + hbase + row * HD + c4);
    }
    CP_COMMIT();
    // ---- group 1: V ----
#pragma unroll
    for (int it = 0; it < 8; it++) {
        int f   = it * 256 + t;
        int row = f >> 4;
        int c4  = (f & 15) << 2;
        CP_ASYNC16(sbV + (row * QP + c4) * 4, g_v + hbase + row * HD + c4);
    }
    CP_COMMIT();

    CP_WAIT1();          // Q, K arrived; V may still be in flight
    __syncthreads();

    // ---- phase 1: S = Q K^T ----
    float sacc[4][4][4];
#pragma unroll
    for (int mt = 0; mt < 4; mt++)
#pragma unroll
        for (int nt = 0; nt < 4; nt++)
#pragma unroll
            for (int r = 0; r < 4; r++) sacc[mt][nt][r] = 0.f;

#pragma unroll
    for (int ks = 0; ks < 8; ks++) {
        uint32_t a[4][4], b[4][2];
#pragma unroll
        for (int mt = 0; mt < 4; mt++) {
            int ar = (wm * 64 + mt * 16 + g) * QP + ks * 8 + tt;
            a[mt][0] = Qs[ar];
            a[mt][1] = Qs[ar + 8 * QP];
            a[mt][2] = Qs[ar + 4];
            a[mt][3] = Qs[ar + 8 * QP + 4];
        }
#pragma unroll
        for (int nt = 0; nt < 4; nt++) {
            int br = (wn * 32 + nt * 8 + g) * QP + ks * 8 + tt;
            b[nt][0] = Ks[br];
            b[nt][1] = Ks[br + 4];
        }
#pragma unroll
        for (int mt = 0; mt < 4; mt++)
#pragma unroll
            for (int nt = 0; nt < 4; nt++)
                mma8(sacc[mt][nt], a[mt], b[nt]);
    }
    __syncthreads();

    const float scale = 0.125f;
#pragma unroll
    for (int mt = 0; mt < 4; mt++) {
        int r0 = (wm * 64 + mt * 16 + g) * SP;
        int r1 = r0 + 8 * SP;
#pragma unroll
        for (int nt = 0; nt < 4; nt++) {
            int c = wn * 32 + nt * 8 + tt * 2;
            Ss[r0 + c]     = sacc[mt][nt][0] * scale;
            Ss[r0 + c + 1] = sacc[mt][nt][1] * scale;
            Ss[r1 + c]     = sacc[mt][nt][2] * scale;
            Ss[r1 + c + 1] = sacc[mt][nt][3] * scale;
        }
    }
    __syncthreads();

    // ---- softmax (poly exp), write P as tf32 ----
    for (int r = warp * 16; r < warp * 16 + 16; r++) {
        float* srow = Ss + r * SP;
        float v0 = srow[lane];
        float v1 = srow[lane + 32];
        float v2 = srow[lane + 64];
        float v3 = srow[lane + 96];
        float mx = fmaxf(fmaxf(v0, v1), fmaxf(v2, v3));
#pragma unroll
        for (int o = 16; o > 0; o >>= 1)
            mx = fmaxf(mx, __shfl_xor_sync(0xffffffffu, mx, o));
        float e0 = fexp(v0 - mx);
        float e1 = fexp(v1 - mx);
        float e2 = fexp(v2 - mx);
        float e3 = fexp(v3 - mx);
        float s = e0 + e1 + e2 + e3;
#pragma unroll
        for (int o = 16; o > 0; o >>= 1)
            s += __shfl_xor_sync(0xffffffffu, s, o);
        float inv = 1.f / s;
        uint32_t* urow = (uint32_t*)srow;
        urow[lane]      = f2tf32(e0 * inv);
        urow[lane + 32] = f2tf32(e1 * inv);
        urow[lane + 64] = f2tf32(e2 * inv);
        urow[lane + 96] = f2tf32(e3 * inv);
    }
    CP_WAIT0();          // V fully arrived (overlapped with S + softmax)
    __syncthreads();

    // ---- phase 2: O = P V ----
    float oacc[4][2][4];
#pragma unroll
    for (int mt = 0; mt < 4; mt++)
#pragma unroll
        for (int nt = 0; nt < 2; nt++)
#pragma unroll
            for (int r = 0; r < 4; r++) oacc[mt][nt][r] = 0.f;

#pragma unroll
    for (int ks = 0; ks < 16; ks++) {
        uint32_t a[4][4], b[2][2];
#pragma unroll
        for (int mt = 0; mt < 4; mt++) {
            int ar = (wm * 64 + mt * 16 + g) * SP + ks * 8 + tt;
            a[mt][0] = Ssu[ar];
            a[mt][1] = Ssu[ar + 8 * SP];
            a[mt][2] = Ssu[ar + 4];
            a[mt][3] = Ssu[ar + 8 * SP + 4];
        }
#pragma unroll
        for (int nt = 0; nt < 2; nt++) {
            int br = (ks * 8 + tt) * QP + wn * 16 + nt * 8 + g;
            b[nt][0] = Vs[br];
            b[nt][1] = Vs[br + 4 * QP];
        }
#pragma unroll
        for (int mt = 0; mt < 4; mt++)
#pragma unroll
            for (int nt = 0; nt < 2; nt++)
                mma8(oacc[mt][nt], a[mt], b[nt]);
    }

    // write O (flat layout), pre-rounded to tf32 for the projection GEMM
#pragma unroll
    for (int mt = 0; mt < 4; mt++) {
        const int row0 = wm * 64 + mt * 16 + g;
#pragma unroll
        for (int nt = 0; nt < 2; nt++) {
            const int c = wn * 16 + nt * 8 + tt * 2;
            float* p0 = g_ao + obase + (size_t)row0 * DM + c;
            float* p1 = g_ao + obase + (size_t)(row0 + 8) * DM + c;
            *(float2*)p0 = make_float2(f2tf32f(oacc[mt][nt][0]), f2tf32f(oacc[mt][nt][1]));
            *(float2*)p1 = make_float2(f2tf32f(oacc[mt][nt][2]), f2tf32f(oacc[mt][nt][3]));
        }
    }
}

// ---------------------------------------------------------------------------
// kernel_launch
// ---------------------------------------------------------------------------
extern "C" void kernel_launch(void* const* d_in, const int* in_sizes, int n_in,
                              void* d_out, int out_size)
{
    const float* x  = (const float*)d_in[0];
    const float* Wq = (const float*)d_in[1];
    const float* bq = (const float*)d_in[2];
    const float* Wk = (const float*)d_in[3];
    const float* bk = (const float*)d_in[4];
    const float* Wv = (const float*)d_in[5];
    const float* bv = (const float*)d_in[6];
    const float* Wp = (const float*)d_in[7];
    const float* bp = (const float*)d_in[8];
    float* out = (float*)d_out;

    void *pq, *pk, *pv, *pao, *pxr, *pwr;
    cudaGetSymbolAddress(&pq,  g_q);
    cudaGetSymbolAddress(&pk,  g_k);
    cudaGetSymbolAddress(&pv,  g_v);
    cudaGetSymbolAddress(&pao, g_ao);
    cudaGetSymbolAddress(&pxr, g_xr);
    cudaGetSymbolAddress(&pwr, g_wr);
    float* gq  = (float*)pq;
    float* gk  = (float*)pk;
    float* gv  = (float*)pv;
    float* gao = (float*)pao;
    float* gxr = (float*)pxr;
    float* gwr = (float*)pwr;

    cudaFuncSetAttribute(gemm_tc,
                         cudaFuncAttributeMaxDynamicSharedMemorySize, GEMM_SMEM_BYTES);
    cudaFuncSetAttribute(attn_kernel,
                         cudaFuncAttributeMaxDynamicSharedMemorySize, ATTN_SMEM_BYTES);

    // pre-pass: round x (1 launch) + all weights (1 launch)
    const int NX4 = MTOT * DM / 4;
    cvt_tf32<<<(NX4 + 255) / 256, 256>>>(x, gxr, NX4);
    dim3 wgrid((DM * DM / 4 + 255) / 256, 4);
    cvt_w4<<<wgrid, 256>>>(Wq, Wk, Wv, Wp, gwr);

    dim3 gblk(256);

    // fused QKV projection: head-major rounded outputs
    dim3 qkvgrid(3 * DM / 128, MTOT / 128);   // (12, 256)
    gemm_tc<<<qkvgrid, gblk, GEMM_SMEM_BYTES>>>(gxr, gwr, bq, bk, bv,
                                                gq, gk, gv, 1);

    dim3 agrid(HEADS, NWIN);                  // (8, 256)
    attn_kernel<<<agrid, gblk, ATTN_SMEM_BYTES>>>();

    // output projection: flat fp32 output, not rounded
    dim3 pgrid(DM / 128, MTOT / 128);         // (4, 256)
    gemm_tc<<<pgrid, gblk, GEMM_SMEM_BYTES>>>(gao, gwr + 3 * DM * DM, bp, bp, bp,
                                              out, out, out, 0);
}